// round 4
// baseline (speedup 1.0000x reference)
#include <cuda_runtime.h>

// x <- gelu(x + depthwise_conv3d_3x3x3(x)) x8.  [4,32,64,64,64] fp32.

#define CC   32
#define VOL  (64*64*64)
#define RS   72                  // slab row stride in words
#define SLABW (18*RS)            // words per slab (18 rows)

typedef unsigned long long u64;
typedef unsigned int u32;

// Ping-pong scratches, padded one D-plane so steady kernels prefetch plane 64 unguarded.
__device__ float  g_sA[4 * CC * VOL + 4096];
__device__ float  g_sB[4 * CC * VOL + 4096];
__device__ __align__(16) float4 g_zero4 = {0.f, 0.f, 0.f, 0.f};

// ---------- packed f32x2 helpers ----------
__device__ __forceinline__ u64 pack2(float lo, float hi) {
    u64 r; asm("mov.b64 %0, {%1, %2};" : "=l"(r) : "f"(lo), "f"(hi)); return r;
}
__device__ __forceinline__ void unpack2(u64 v, float& lo, float& hi) {
    asm("mov.b64 {%0, %1}, %2;" : "=f"(lo), "=f"(hi) : "l"(v));
}
__device__ __forceinline__ void fma2(u64& acc, u64 a, u64 b) {
    asm("fma.rn.f32x2 %0, %1, %2, %0;" : "+l"(acc) : "l"(a), "l"(b));
}
__device__ __forceinline__ void mul2(u64& d, u64 a, u64 b) {
    asm("mul.rn.f32x2 %0, %1, %2;" : "=l"(d) : "l"(a), "l"(b));
}
__device__ __forceinline__ u64 add2(u64 a, u64 b) {
    u64 r; asm("add.rn.f32x2 %0, %1, %2;" : "=l"(r) : "l"(a), "l"(b)); return r;
}

// ---------- shared-memory access (u32 smem addresses) ----------
// MUST be volatile: plain asm (register-only inputs) would be CSE'd across
// planes (identical addresses every 3rd plane) and hoisted over __syncthreads /
// cp.async.wait_group — that was the round-3 correctness bug.
__device__ __forceinline__ float lds1(u32 a) {
    float v; asm volatile("ld.shared.f32 %0, [%1];" : "=f"(v) : "r"(a)); return v;
}
__device__ __forceinline__ float2 lds2(u32 a) {
    float2 v; asm volatile("ld.shared.v2.f32 {%0, %1}, [%2];"
                           : "=f"(v.x), "=f"(v.y) : "r"(a)); return v;
}
__device__ __forceinline__ void ldw3(u32 a, u64& x, u64& y, u64& z) {
    asm volatile("ld.shared.v2.u64 {%0, %1}, [%2];" : "=l"(x), "=l"(y) : "r"(a));
    asm volatile("ld.shared.u64 %0, [%1];" : "=l"(z) : "r"(a + 16));
}
__device__ __forceinline__ void cpa16(u32 d, const void* s) {
    asm volatile("cp.async.cg.shared.global [%0], [%1], 16;" :: "r"(d), "l"(s));
}
__device__ __forceinline__ void cpa16_pred(int pred, u32 d, const void* s) {
    asm volatile("{ .reg .pred p; setp.ne.s32 p, %0, 0;"
                 "  @p cp.async.cg.shared.global [%1], [%2], 16; }"
                 :: "r"(pred), "r"(d), "l"(s));
}

// Exact-erf GELU via A&S 7.1.26 (abs err ~1.5e-7, tol is 1e-3).
__device__ __forceinline__ float gelu_exact(float x) {
    float z = x * 0.70710678118654752440f;
    float a = fabsf(z);
    float d = fmaf(0.3275911f, a, 1.0f);
    float t; asm("rcp.approx.f32 %0, %1;" : "=f"(t) : "f"(d));
    float p = fmaf(t, 1.061405429f, -1.453152027f);
    p = fmaf(t, p, 1.421413741f);
    p = fmaf(t, p, -0.284496736f);
    p = fmaf(t, p, 0.254829592f);
    p = p * t;
    float e; asm("ex2.approx.f32 %0, %1;" : "=f"(e) : "f"(-a * a * 1.4426950408889634f));
    float er = fmaf(-p, e, 1.0f);
    er = copysignf(er, z);
    return 0.5f * fmaf(x, er, x);
}

// One ky-row: 6-float window (1+v2+v2+1 LDS), 5 f32x2 windows, weights from SMEM
// (three aligned triples), 18 fma2 into accumulators X (completes), Y (mid), Z (fresh).
#define ROW(RB, r, FIRSTZ, CAPC)                                                 \
    {                                                                            \
        u32 a_ = (RB) + (r) * (RS * 4);                                          \
        float  f0 = lds1(a_);                                                    \
        float2 m1 = lds2(a_ + 4);                                                \
        float2 m2 = lds2(a_ + 12);                                               \
        float  f5 = lds1(a_ + 20);                                               \
        u64 P0 = pack2(f0,   m1.x), P1 = pack2(m1.x, m1.y);                      \
        u64 P2 = pack2(m1.y, m2.x), P3 = pack2(m2.x, m2.y);                      \
        u64 P4 = pack2(m2.y, f5);                                                \
        if (CAPC) { CN0 = P1; CN1 = P3; }                                        \
        u64 wa, wb, wc;                                                          \
        ldw3(swa + (6 + (r)) * 32, wa, wb, wc);                                  \
        fma2(X0, wa, P0); fma2(X1, wa, P2); fma2(X0, wb, P1);                    \
        fma2(X1, wb, P3); fma2(X0, wc, P2); fma2(X1, wc, P4);                    \
        ldw3(swa + (3 + (r)) * 32, wa, wb, wc);                                  \
        fma2(Y0, wa, P0); fma2(Y1, wa, P2); fma2(Y0, wb, P1);                    \
        fma2(Y1, wb, P3); fma2(Y0, wc, P2); fma2(Y1, wc, P4);                    \
        ldw3(swa + (r) * 32, wa, wb, wc);                                        \
        if (FIRSTZ) { mul2(Z0, wa, P0); mul2(Z1, wa, P2); }                      \
        else        { fma2(Z0, wa, P0); fma2(Z1, wa, P2); }                      \
        fma2(Z0, wb, P1); fma2(Z1, wb, P3); fma2(Z0, wc, P2); fma2(Z1, wc, P4);  \
    }

// One plane P: issue async copies of plane P+1 into slab DN, commit, wait for
// plane P's copies, barrier, accumulate 3 rows from RB, store completed out(P-1).
#define BODY(P, DN, RB, _X0,_X1,_Y0,_Y1,_Z0,_Z1, CP0,CP1, _CN0,_CN1, DOSTORE)    \
    do {                                                                         \
        const char* sA_ = pA; const char* sB_ = pB;                              \
        if (GUARD && (P) == 63) {                                                \
            sA_ = (const char*)&g_zero4; sB_ = (const char*)&g_zero4;            \
        }                                                                        \
        cpa16(DN, sA_);                                                          \
        cpa16_pred(isB, (DN) + 4608, sB_);                                       \
        asm volatile("cp.async.commit_group;");                                  \
        pA += stA; pB += stB;                                                    \
        asm volatile("cp.async.wait_group 1;");                                  \
        __syncthreads();                                                         \
        {                                                                        \
            u64 &X0=_X0, &X1=_X1, &Y0=_Y0, &Y1=_Y1, &Z0=_Z0, &Z1=_Z1;           \
            u64 &CN0=_CN0, &CN1=_CN1;                                            \
            ROW(RB, 0, true,  false)                                             \
            ROW(RB, 1, false, true)                                              \
            ROW(RB, 2, false, false)                                             \
            if (DOSTORE) {                                                       \
                u64 u0 = add2(X0, CP0), u1 = add2(X1, CP1);                      \
                float o0,o1,o2,o3; unpack2(u0,o0,o1); unpack2(u1,o2,o3);         \
                float4 ov = make_float4(gelu_exact(o0), gelu_exact(o1),          \
                                        gelu_exact(o2), gelu_exact(o3));         \
                *(float4*)optr = ov;                                             \
            }                                                                    \
        }                                                                        \
        optr += 16384;                                                           \
    } while (0)

template<bool GUARD>
__global__ void __launch_bounds__(256, 4)
step_kernel(const float* __restrict__ in, float* __restrict__ out,
            const float* __restrict__ wts)
{
    const int tx  = threadIdx.x;             // 0..15 (w quads)
    const int ty  = threadIdx.y;             // 0..15 (h rows)
    const int tid = ty * 16 + tx;
    const int h0  = blockIdx.x * 16;
    const int c   = blockIdx.y;
    const int b   = blockIdx.z;

    const float* vin  = in  + (size_t)(b * CC + c) * VOL;
    float*       vout = out + (size_t)(b * CC + c) * VOL;

    // SMEM: 3 triple-buffered slabs (rows 0..17, data words 4..67, halos 3 & 68)
    // + weights as u64 (w,w) pairs in 9 aligned triples.
    __shared__ __align__(16) float slab[3][SLABW];
    __shared__ __align__(16) u64   sw[36];

    if (tid < 27) {                          // weights -> smem as (w,w) pairs
        int kz = tid / 9, ky = (tid % 9) / 3, kx = tid % 3;
        float w = __ldg(&wts[c * 27 + tid]);
        sw[(kz * 3 + ky) * 4 + kx] = pack2(w, w);
    }
    if (tid < 108) {                         // zero W-halo words (3 & 68), all rows, all slabs
        int s = tid / 36, k = tid % 36;
        slab[s][(k % 18) * RS + (k < 18 ? 3 : 68)] = 0.f;
    }

    const u32 sbase = (u32)__cvta_generic_to_shared(slab);
    const u32 swa   = (u32)__cvta_generic_to_shared(sw);

    // Loader geometry: rows r0 (all threads) and r0+16 (warp 0 only).
    const int  r0  = tid >> 4, cq = tid & 15;
    const int  gh0 = h0 - 1 + r0;
    const bool v0  = (gh0 >= 0) && (gh0 < 64);
    const char* pA = v0 ? (const char*)((const float4*)vin + gh0 * 16 + cq)
                        : (const char*)&g_zero4;
    const int  stA = v0 ? 16384 : 0;

    const int  r1  = 16 + r0;
    const int  gh1 = h0 - 1 + r1;
    const bool v1  = (tid < 32) && (gh1 < 64);
    const char* pB = v1 ? (const char*)((const float4*)vin + gh1 * 16 + cq)
                        : (const char*)&g_zero4;
    const int  stB = v1 ? 16384 : 0;
    const int  isB = (tid < 32) ? 1 : 0;

    const u32 dA0 = sbase + (r0 * RS + 4 + 4 * cq) * 4;   // +4608 bytes = row r0+16
    const u32 dA1 = dA0 + SLABW * 4;
    const u32 dA2 = dA0 + 2 * SLABW * 4;
    const u32 rb0 = sbase + (ty * RS + 3 + 4 * tx) * 4;
    const u32 rb1 = rb0 + SLABW * 4;
    const u32 rb2 = rb0 + 2 * SLABW * 4;

    // Prologue: async-copy plane 0 into slab 0.
    cpa16(dA0, pA);
    cpa16_pred(isB, dA0 + 4608, pB);
    asm volatile("cp.async.commit_group;");
    pA += stA; pB += stB;

    u64 x0=0,x1=0,y0=0,y1=0,z0=0,z1=0;       // rotating accumulators (static roles)
    u64 cA0=0,cA1=0,cB0=0,cB1=0;             // rotating residual centers

    char* optr = (char*)(vout + ((h0 + ty) * 64 + 4 * tx)) - 16384;

    // Peel planes 0..3 (period-6 alignment: slab %3, roles %3, centers %2).
    BODY(0, dA1, rb0, x0,x1,y0,y1,z0,z1, cA0,cA1, cB0,cB1, false);
    BODY(1, dA2, rb1, y0,y1,z0,z1,x0,x1, cB0,cB1, cA0,cA1, true);
    BODY(2, dA0, rb2, z0,z1,x0,x1,y0,y1, cA0,cA1, cB0,cB1, true);
    BODY(3, dA1, rb0, x0,x1,y0,y1,z0,z1, cB0,cB1, cA0,cA1, true);

#pragma unroll 1
    for (int i = 0; i < 10; ++i) {           // planes 4..63
        const int p = 4 + 6 * i;
        BODY(p+0, dA2, rb1, y0,y1,z0,z1,x0,x1, cA0,cA1, cB0,cB1, true);
        BODY(p+1, dA0, rb2, z0,z1,x0,x1,y0,y1, cB0,cB1, cA0,cA1, true);
        BODY(p+2, dA1, rb0, x0,x1,y0,y1,z0,z1, cA0,cA1, cB0,cB1, true);
        BODY(p+3, dA2, rb1, y0,y1,z0,z1,x0,x1, cB0,cB1, cA0,cA1, true);
        BODY(p+4, dA0, rb2, z0,z1,x0,x1,y0,y1, cA0,cA1, cB0,cB1, true);
        BODY(p+5, dA1, rb0, x0,x1,y0,y1,z0,z1, cB0,cB1, cA0,cA1, true);
    }

    // out(63): kz2 (plane 64) is zero padding; partial in y, center in cA.
    {
        u64 u0 = add2(y0, cA0), u1 = add2(y1, cA1);
        float o0,o1,o2,o3; unpack2(u0,o0,o1); unpack2(u1,o2,o3);
        float4 ov = make_float4(gelu_exact(o0), gelu_exact(o1),
                                gelu_exact(o2), gelu_exact(o3));
        *(float4*)optr = ov;
    }
}

extern "C" void kernel_launch(void* const* d_in, const int* in_sizes, int n_in,
                              void* d_out, int out_size)
{
    const float* x = (const float*)d_in[0];
    const float* w = (const float*)d_in[1];
    float* out = (float*)d_out;

    float *sA = nullptr, *sB = nullptr;
    cudaGetSymbolAddress((void**)&sA, g_sA);
    cudaGetSymbolAddress((void**)&sB, g_sB);

    dim3 grid(4, CC, 4);
    dim3 blk(16, 16);

    step_kernel<true ><<<grid, blk>>>(x,  sA,  w);
    step_kernel<false><<<grid, blk>>>(sA, sB,  w);
    step_kernel<false><<<grid, blk>>>(sB, sA,  w);
    step_kernel<false><<<grid, blk>>>(sA, sB,  w);
    step_kernel<false><<<grid, blk>>>(sB, sA,  w);
    step_kernel<false><<<grid, blk>>>(sA, sB,  w);
    step_kernel<false><<<grid, blk>>>(sB, sA,  w);
    step_kernel<false><<<grid, blk>>>(sA, out, w);
}